// round 7
// baseline (speedup 1.0000x reference)
#include <cuda_runtime.h>
#include <cuda_bf16.h>

#define N_NODES   100000
#define N_EDGES   3200000
#define N_GRAPHS  256
#define FEAT      128
#define FPITCH    36   // fp32 smem pitch (conflict-free frag loads, float4-aligned)

// ---------------- scratch ----------------
__device__ __align__(16) int   g_cnt[N_NODES];
__device__ __align__(16) int   g_fill[N_NODES];
__device__ __align__(16) int   g_rowstart[N_NODES];
__device__ __align__(16) int   g_bsum[512];
__device__ __align__(16) float g_dis[N_NODES];
__device__ __align__(16) int2  g_cv[N_EDGES];
__device__ __align__(16) __nv_bfloat16 g_hb[(size_t)N_NODES * FEAT];  // GEMM out (bf16, gathered)
__device__ __align__(16) float g_a[(size_t)N_NODES * FEAT];           // agg out (fp32, post-relu)
__device__ __align__(16) float g_wtf[3 * FEAT * FEAT];                // Wt tf32-rounded [l][n][k]
__device__ __align__(16) float g_pool[N_GRAPHS * FEAT];
__device__ int g_is64;

__device__ __forceinline__ int ld_idx(const int* __restrict__ p, long long i, int is64) {
    if (is64) return (int)(((const long long*)p)[i]);
    return p[i];
}

__device__ __forceinline__ unsigned f2tf32(float f) {
    unsigned r;
    asm("cvt.rna.tf32.f32 %0, %1;" : "=r"(r) : "f"(f));
    return r;
}

// ---------------- dtype sniff ----------------
__global__ void k_sniff(const int* __restrict__ ei) {
    if (threadIdx.x == 0 && blockIdx.x == 0) {
        int odd = 0;
        for (int i = 1; i < 128; i += 2) odd |= ei[i];
        g_is64 = (odd == 0) ? 1 : 0;
    }
}

// ---------------- prep ----------------
__global__ void k_zero(int n) {
    int i = blockIdx.x * blockDim.x + threadIdx.x;
    if (i < n) { g_cnt[i] = 0; g_fill[i] = 0; }
}

__global__ void k_count(const int* __restrict__ ei, int E, int n) {
    int e = blockIdx.x * blockDim.x + threadIdx.x;
    if (e >= E) return;
    int d = ld_idx(ei, (long long)E + e, g_is64);
    if ((unsigned)d < (unsigned)n) atomicAdd(&g_cnt[d], 1);
}

__global__ void k_dis(int n) {
    int i = blockIdx.x * blockDim.x + threadIdx.x;
    if (i < n) g_dis[i] = rsqrtf((float)g_cnt[i] + 1.0f);
}

__global__ void k_scan1(int n) {
    __shared__ int s[256];
    int t = threadIdx.x;
    int i = blockIdx.x * 256 + t;
    int v = (i < n) ? g_cnt[i] : 0;
    s[t] = v; __syncthreads();
    for (int off = 1; off < 256; off <<= 1) {
        int a = (t >= off) ? s[t - off] : 0;
        __syncthreads();
        s[t] += a;
        __syncthreads();
    }
    if (i < n) g_rowstart[i] = s[t] - v;
    if (t == 255) g_bsum[blockIdx.x] = s[255];
}

__global__ void k_scan2(int nb) {
    __shared__ int s[512];
    int t = threadIdx.x;
    int v = (t < nb) ? g_bsum[t] : 0;
    s[t] = v; __syncthreads();
    for (int off = 1; off < 512; off <<= 1) {
        int a = (t >= off) ? s[t - off] : 0;
        __syncthreads();
        s[t] += a;
        __syncthreads();
    }
    if (t < nb) g_bsum[t] = s[t] - v;
}

__global__ void k_scan3(int n) {
    int i = blockIdx.x * 256 + threadIdx.x;
    if (i < n) g_rowstart[i] += g_bsum[blockIdx.x];
}

__global__ void k_fillcsr(const int* __restrict__ ei, int E, int n) {
    int e = blockIdx.x * blockDim.x + threadIdx.x;
    if (e >= E) return;
    int is64 = g_is64;
    int s = ld_idx(ei, e, is64);
    int d = ld_idx(ei, (long long)E + e, is64);
    if ((unsigned)s >= (unsigned)n || (unsigned)d >= (unsigned)n) return;
    int pos = atomicAdd(&g_fill[d], 1);
    float v = g_dis[s] * g_dis[d];
    g_cv[g_rowstart[d] + pos] = make_int2(s, __float_as_int(v));
}

// ---------------- weight transpose + tf32 round: g_wtf[l][n][k] = tf32(W_l[k][n]) ----------------
__global__ void k_convw(const float* __restrict__ W1, const float* __restrict__ W2,
                        const float* __restrict__ W3) {
    int i = blockIdx.x * 256 + threadIdx.x;
    if (i >= 3 * FEAT * FEAT) return;
    int layer = i >> 14;
    int r = i & 16383;
    int nn = r >> 7, k = r & 127;
    const float* W = (layer == 0) ? W1 : (layer == 1) ? W2 : W3;
    g_wtf[i] = __uint_as_float(f2tf32(W[k * FEAT + nn]));
}

// ---------------- tf32 tensor-core GEMM: g_hb[n,128] = A[n,128] @ W[128,128] ----------------
// 128x128 block tile, 8 warps (2x4), warp tile 64x32, mma m16n8k8 tf32->fp32, K chunk 32.
__global__ __launch_bounds__(256) void k_gemm_mma(const float* __restrict__ Ain,
                                                  int layer, int n) {
    __shared__ float As[128][FPITCH];
    __shared__ float Bs[128][FPITCH];   // Bs[nn][k]

    const float* A  = Ain ? Ain : g_a;
    const float* Wt = g_wtf + (size_t)layer * FEAT * FEAT;

    int tid  = threadIdx.x;
    int wid  = tid >> 5;
    int lane = tid & 31;
    int gID  = lane >> 2;
    int t4   = lane & 3;
    int row0 = blockIdx.x << 7;
    int wm0  = (wid & 1) << 6;   // 0/64
    int wn0  = (wid >> 1) << 5;  // 0/32/64/96

    float acc[4][4][4];
#pragma unroll
    for (int mi = 0; mi < 4; mi++)
#pragma unroll
        for (int ni = 0; ni < 4; ni++)
#pragma unroll
            for (int c = 0; c < 4; c++) acc[mi][ni][c] = 0.f;

    for (int k0 = 0; k0 < 128; k0 += 32) {
        // stage A chunk [128][32] with tf32 rounding
        for (int it = tid; it < 1024; it += 256) {
            int r = it >> 3, c4 = (it & 7) << 2;
            float4 v = make_float4(0.f, 0.f, 0.f, 0.f);
            if (row0 + r < n) v = *(const float4*)(A + (size_t)(row0 + r) * FEAT + k0 + c4);
            v.x = __uint_as_float(f2tf32(v.x));
            v.y = __uint_as_float(f2tf32(v.y));
            v.z = __uint_as_float(f2tf32(v.z));
            v.w = __uint_as_float(f2tf32(v.w));
            *(float4*)(&As[r][c4]) = v;
        }
        // stage Wt chunk [128][32] (already tf32-rounded)
        for (int it = tid; it < 1024; it += 256) {
            int nn = it >> 3, c4 = (it & 7) << 2;
            *(float4*)(&Bs[nn][c4]) = *(const float4*)(Wt + (size_t)nn * FEAT + k0 + c4);
        }
        __syncthreads();

#pragma unroll
        for (int ks = 0; ks < 32; ks += 8) {
            unsigned a[4][4], b[4][2];
#pragma unroll
            for (int mi = 0; mi < 4; mi++) {
                int m = wm0 + (mi << 4);
                a[mi][0] = __float_as_uint(As[m + gID][ks + t4]);
                a[mi][1] = __float_as_uint(As[m + gID + 8][ks + t4]);
                a[mi][2] = __float_as_uint(As[m + gID][ks + t4 + 4]);
                a[mi][3] = __float_as_uint(As[m + gID + 8][ks + t4 + 4]);
            }
#pragma unroll
            for (int ni = 0; ni < 4; ni++) {
                int nn = wn0 + (ni << 3);
                b[ni][0] = __float_as_uint(Bs[nn + gID][ks + t4]);
                b[ni][1] = __float_as_uint(Bs[nn + gID][ks + t4 + 4]);
            }
#pragma unroll
            for (int mi = 0; mi < 4; mi++)
#pragma unroll
                for (int ni = 0; ni < 4; ni++) {
                    asm volatile(
                        "mma.sync.aligned.m16n8k8.row.col.f32.tf32.tf32.f32 "
                        "{%0,%1,%2,%3}, {%4,%5,%6,%7}, {%8,%9}, {%0,%1,%2,%3};\n"
                        : "+f"(acc[mi][ni][0]), "+f"(acc[mi][ni][1]),
                          "+f"(acc[mi][ni][2]), "+f"(acc[mi][ni][3])
                        : "r"(a[mi][0]), "r"(a[mi][1]), "r"(a[mi][2]), "r"(a[mi][3]),
                          "r"(b[ni][0]), "r"(b[ni][1]));
                }
        }
        __syncthreads();
    }

    // epilogue: fp32 acc -> bf16 g_hb
#pragma unroll
    for (int mi = 0; mi < 4; mi++) {
        int r0 = row0 + wm0 + (mi << 4) + gID;
        int r1 = r0 + 8;
#pragma unroll
        for (int ni = 0; ni < 4; ni++) {
            int col = wn0 + (ni << 3) + (t4 << 1);
            if (r0 < n) {
                __nv_bfloat162 p = __floats2bfloat162_rn(acc[mi][ni][0], acc[mi][ni][1]);
                *(__nv_bfloat162*)(g_hb + (size_t)r0 * FEAT + col) = p;
            }
            if (r1 < n) {
                __nv_bfloat162 p = __floats2bfloat162_rn(acc[mi][ni][2], acc[mi][ni][3]);
                *(__nv_bfloat162*)(g_hb + (size_t)r1 * FEAT + col) = p;
            }
        }
    }
}

// ---------------- aggregation: g_a[i] = relu(b + dis^2*hb[i] + sum val*hb[col]) ----------------
__global__ void k_agg(const float* __restrict__ bias, int n) {
    int w = (blockIdx.x * blockDim.x + threadIdx.x) >> 5;
    int lane = threadIdx.x & 31;
    if (w >= n) return;
    int start = g_rowstart[w];
    int m = g_cnt[w];
    float d = g_dis[w];
    float dd = d * d;

    uint2 sv = *((const uint2*)(g_hb + (size_t)w * FEAT) + lane);
    float2 s0 = __bfloat1622float2(*(const __nv_bfloat162*)&sv.x);
    float2 s1 = __bfloat1622float2(*(const __nv_bfloat162*)&sv.y);
    float4 bv = __ldg((const float4*)bias + lane);
    float4 acc;
    acc.x = bv.x + s0.x * dd;
    acc.y = bv.y + s0.y * dd;
    acc.z = bv.z + s1.x * dd;
    acc.w = bv.w + s1.y * dd;

    for (int j = 0; j < m; j++) {
        int2 cv = g_cv[start + j];
        float v = __int_as_float(cv.y);
        uint2 hm = *((const uint2*)(g_hb + (size_t)cv.x * FEAT) + lane);
        float2 f0 = __bfloat1622float2(*(const __nv_bfloat162*)&hm.x);
        float2 f1 = __bfloat1622float2(*(const __nv_bfloat162*)&hm.y);
        acc.x = fmaf(f0.x, v, acc.x);
        acc.y = fmaf(f0.y, v, acc.y);
        acc.z = fmaf(f1.x, v, acc.z);
        acc.w = fmaf(f1.y, v, acc.w);
    }
    acc.x = fmaxf(acc.x, 0.f);
    acc.y = fmaxf(acc.y, 0.f);
    acc.z = fmaxf(acc.z, 0.f);
    acc.w = fmaxf(acc.w, 0.f);
    ((float4*)(g_a + (size_t)w * FEAT))[lane] = acc;
}

// ---------------- mean pool (fp32 in, already relu'd) ----------------
__global__ void k_pool(const int* __restrict__ batch, int n) {
    int g = blockIdx.x;
    int f = threadIdx.x;
    int is64 = g_is64;
    int lo = 0, hi = n;
    while (lo < hi) { int mid = (lo + hi) >> 1; if (ld_idx(batch, mid, is64) < g) lo = mid + 1; else hi = mid; }
    int s = lo;
    hi = n;
    while (lo < hi) { int mid = (lo + hi) >> 1; if (ld_idx(batch, mid, is64) <= g) lo = mid + 1; else hi = mid; }
    int e = lo;
    float acc = 0.f;
    for (int i = s; i < e; i++) acc += g_a[(size_t)i * FEAT + f];
    int c = e - s;
    g_pool[g * FEAT + f] = acc / (float)(c > 0 ? c : 1);
}

// ---------------- MLP head ----------------
__global__ void k_mlp(const float* __restrict__ w1, const float* __restrict__ b1,
                      const float* __restrict__ w2, const float* __restrict__ b2,
                      float* __restrict__ out) {
    int g = blockIdx.x;
    int t = threadIdx.x;  // 128
    __shared__ float gs[128];
    __shared__ float ts[128];
    gs[t] = g_pool[g * FEAT + t];
    __syncthreads();
    float acc = b1[t];
#pragma unroll 8
    for (int k = 0; k < 128; k++) acc = fmaf(gs[k], w1[k * 128 + t], acc);
    ts[t] = fmaxf(acc, 0.f);
    __syncthreads();
    if (t < 10) {
        float o = b2[t];
#pragma unroll 8
        for (int j = 0; j < 128; j++) o = fmaf(ts[j], w2[j * 10 + t], o);
        out[g * 10 + t] = o;
    }
}

// ---------------- launcher ----------------
extern "C" void kernel_launch(void* const* d_in, const int* in_sizes, int n_in,
                              void* d_out, int out_size) {
    const float* x     = (const float*)d_in[0];
    const int*   ei    = (const int*)d_in[1];
    const int*   batch = (const int*)d_in[2];
    const float* W1 = (const float*)d_in[3];  const float* b1 = (const float*)d_in[4];
    const float* W2 = (const float*)d_in[5];  const float* b2 = (const float*)d_in[6];
    const float* W3 = (const float*)d_in[7];  const float* b3 = (const float*)d_in[8];
    const float* l1w = (const float*)d_in[9];  const float* l1b = (const float*)d_in[10];
    const float* l2w = (const float*)d_in[11]; const float* l2b = (const float*)d_in[12];
    float* out = (float*)d_out;

    int n = in_sizes[0] / FEAT;   // 100000
    int E = in_sizes[1] / 2;      // 3200000

    int nb = (n + 255) / 256;
    int eb = (E + 255) / 256;
    int gb = (n + 127) / 128;
    long long athreads = (long long)n * 32;
    int ab = (int)((athreads + 255) / 256);

    k_sniff  <<<1, 32>>>(ei);
    k_zero   <<<nb, 256>>>(n);
    k_count  <<<eb, 256>>>(ei, E, n);
    k_dis    <<<nb, 256>>>(n);
    k_scan1  <<<nb, 256>>>(n);
    k_scan2  <<<1, 512>>>(nb);
    k_scan3  <<<nb, 256>>>(n);
    k_fillcsr<<<eb, 256>>>(ei, E, n);
    k_convw  <<<192, 256>>>(W1, W2, W3);

    k_gemm_mma<<<gb, 256>>>(x, 0, n);
    k_agg     <<<ab, 256>>>(b1, n);
    k_gemm_mma<<<gb, 256>>>(nullptr, 1, n);
    k_agg     <<<ab, 256>>>(b2, n);
    k_gemm_mma<<<gb, 256>>>(nullptr, 2, n);
    k_agg     <<<ab, 256>>>(b3, n);

    k_pool<<<N_GRAPHS, 128>>>(batch, n);
    k_mlp <<<N_GRAPHS, 128>>>(l1w, l1b, l2w, l2b, out);
}

// round 9
// speedup vs baseline: 1.1590x; 1.1590x over previous
#include <cuda_runtime.h>
#include <cuda_bf16.h>
#include <cstdint>

#define N_NODES   100000
#define N_EDGES   3200000
#define N_GRAPHS  256
#define FEAT      128

// ---------------- scratch ----------------
__device__ __align__(16) int   g_cnt[N_NODES];
__device__ __align__(16) int   g_fill[N_NODES];
__device__ __align__(16) int   g_rowstart[N_NODES];
__device__ __align__(16) int   g_bsum[512];
__device__ __align__(16) float g_dis[N_NODES];
__device__ __align__(16) int2  g_cv[N_EDGES];
__device__ __align__(16) __nv_bfloat16 g_hb[(size_t)N_NODES * FEAT];  // GEMM out (bf16, gathered)
__device__ __align__(16) float g_a[(size_t)N_NODES * FEAT];           // agg out (fp32, post-relu)
__device__ __align__(16) float g_pool[N_GRAPHS * FEAT];
__device__ int g_is64;

__device__ __forceinline__ int ld_idx(const int* __restrict__ p, long long i, int is64) {
    if (is64) return (int)(((const long long*)p)[i]);
    return p[i];
}

// ---------------- dtype sniff ----------------
__global__ void k_sniff(const int* __restrict__ ei) {
    if (threadIdx.x == 0 && blockIdx.x == 0) {
        int odd = 0;
        for (int i = 1; i < 128; i += 2) odd |= ei[i];
        g_is64 = (odd == 0) ? 1 : 0;
    }
}

// ---------------- prep ----------------
__global__ void k_zero(int n) {
    int i = blockIdx.x * blockDim.x + threadIdx.x;
    if (i < n) { g_cnt[i] = 0; g_fill[i] = 0; }
}
__global__ void k_count(const int* __restrict__ ei, int E, int n) {
    int e = blockIdx.x * blockDim.x + threadIdx.x;
    if (e >= E) return;
    int d = ld_idx(ei, (long long)E + e, g_is64);
    if ((unsigned)d < (unsigned)n) atomicAdd(&g_cnt[d], 1);
}
__global__ void k_dis(int n) {
    int i = blockIdx.x * blockDim.x + threadIdx.x;
    if (i < n) g_dis[i] = rsqrtf((float)g_cnt[i] + 1.0f);
}
__global__ void k_scan1(int n) {
    __shared__ int s[256];
    int t = threadIdx.x;
    int i = blockIdx.x * 256 + t;
    int v = (i < n) ? g_cnt[i] : 0;
    s[t] = v; __syncthreads();
    for (int off = 1; off < 256; off <<= 1) {
        int a = (t >= off) ? s[t - off] : 0;
        __syncthreads();
        s[t] += a;
        __syncthreads();
    }
    if (i < n) g_rowstart[i] = s[t] - v;
    if (t == 255) g_bsum[blockIdx.x] = s[255];
}
__global__ void k_scan2(int nb) {
    __shared__ int s[512];
    int t = threadIdx.x;
    int v = (t < nb) ? g_bsum[t] : 0;
    s[t] = v; __syncthreads();
    for (int off = 1; off < 512; off <<= 1) {
        int a = (t >= off) ? s[t - off] : 0;
        __syncthreads();
        s[t] += a;
        __syncthreads();
    }
    if (t < nb) g_bsum[t] = s[t] - v;
}
__global__ void k_scan3(int n) {
    int i = blockIdx.x * 256 + threadIdx.x;
    if (i < n) g_rowstart[i] += g_bsum[blockIdx.x];
}
__global__ void k_fillcsr(const int* __restrict__ ei, int E, int n) {
    int e = blockIdx.x * blockDim.x + threadIdx.x;
    if (e >= E) return;
    int is64 = g_is64;
    int s = ld_idx(ei, e, is64);
    int d = ld_idx(ei, (long long)E + e, is64);
    if ((unsigned)s >= (unsigned)n || (unsigned)d >= (unsigned)n) return;
    int pos = atomicAdd(&g_fill[d], 1);
    float v = g_dis[s] * g_dis[d];
    g_cv[g_rowstart[d] + pos] = make_int2(s, __float_as_int(v));
}

// ---------------- GEMM: g_hb[n,128] = A[n,128] @ W[128,128] (packed fma.rn.f32x2) ----------------
__global__ __launch_bounds__(256) void k_gemmW(const float* __restrict__ Ain,
                                               const float* __restrict__ W, int n) {
    __shared__ float As[32][129];
    __shared__ float Ws[32][128];
    const float* A = Ain ? Ain : g_a;
    int tid = threadIdx.x;
    int row0 = blockIdx.x << 7;
    int tx = tid & 15, ty = tid >> 4;
    int m0 = ty << 3, n0 = tx << 3;

    unsigned long long acc2[8][4];
#pragma unroll
    for (int i = 0; i < 8; i++)
#pragma unroll
        for (int j = 0; j < 4; j++) acc2[i][j] = 0ull;

#pragma unroll 1
    for (int k0 = 0; k0 < 128; k0 += 32) {
        for (int it = tid; it < 1024; it += 256) {
            int r = it >> 3, c4 = (it & 7) << 2;
            float4 v = make_float4(0.f, 0.f, 0.f, 0.f);
            if (row0 + r < n) v = *(const float4*)(A + (size_t)(row0 + r) * FEAT + k0 + c4);
            As[c4 + 0][r] = v.x;
            As[c4 + 1][r] = v.y;
            As[c4 + 2][r] = v.z;
            As[c4 + 3][r] = v.w;
        }
        for (int it = tid; it < 1024; it += 256) {
            int k = it >> 5, c4 = (it & 31) << 2;
            *(float4*)(&Ws[k][c4]) = *(const float4*)(W + (size_t)(k0 + k) * FEAT + c4);
        }
        __syncthreads();

#pragma unroll
        for (int k = 0; k < 32; k++) {
            ulonglong2 bq0 = *(ulonglong2*)(&Ws[k][n0]);
            ulonglong2 bq1 = *(ulonglong2*)(&Ws[k][n0 + 4]);
            unsigned long long bp0 = bq0.x, bp1 = bq0.y, bp2 = bq1.x, bp3 = bq1.y;
#pragma unroll
            for (int i = 0; i < 8; i++) {
                float a = As[k][m0 + i];
                unsigned long long ap;
                asm("mov.b64 %0, {%1, %1};" : "=l"(ap) : "f"(a));
                asm("fma.rn.f32x2 %0, %1, %2, %0;" : "+l"(acc2[i][0]) : "l"(ap), "l"(bp0));
                asm("fma.rn.f32x2 %0, %1, %2, %0;" : "+l"(acc2[i][1]) : "l"(ap), "l"(bp1));
                asm("fma.rn.f32x2 %0, %1, %2, %0;" : "+l"(acc2[i][2]) : "l"(ap), "l"(bp2));
                asm("fma.rn.f32x2 %0, %1, %2, %0;" : "+l"(acc2[i][3]) : "l"(ap), "l"(bp3));
            }
        }
        __syncthreads();
    }

#pragma unroll
    for (int i = 0; i < 8; i++) {
        int r = row0 + m0 + i;
        if (r < n) {
            uint32_t o[4];
#pragma unroll
            for (int j = 0; j < 4; j++) {
                uint32_t lo, hi;
                asm("mov.b64 {%0, %1}, %2;" : "=r"(lo), "=r"(hi) : "l"(acc2[i][j]));
                __nv_bfloat162 p = __floats2bfloat162_rn(__uint_as_float(lo), __uint_as_float(hi));
                o[j] = *(uint32_t*)&p;
            }
            *(uint4*)(g_hb + (size_t)r * FEAT + n0) = make_uint4(o[0], o[1], o[2], o[3]);
        }
    }
}

// ---------------- aggregation: g_a[i] = relu(b + dis^2*hb[i] + sum val*hb[col]) ----------------
__global__ void k_agg(const float* __restrict__ bias, int n) {
    int w = (blockIdx.x * blockDim.x + threadIdx.x) >> 5;
    int lane = threadIdx.x & 31;
    if (w >= n) return;
    int start = g_rowstart[w];
    int m = g_cnt[w];
    float d = g_dis[w];
    float dd = d * d;

    uint2 sv = *((const uint2*)(g_hb + (size_t)w * FEAT) + lane);
    float2 s0 = __bfloat1622float2(*(const __nv_bfloat162*)&sv.x);
    float2 s1 = __bfloat1622float2(*(const __nv_bfloat162*)&sv.y);
    float4 bv = __ldg((const float4*)bias + lane);
    float4 acc;
    acc.x = bv.x + s0.x * dd;
    acc.y = bv.y + s0.y * dd;
    acc.z = bv.z + s1.x * dd;
    acc.w = bv.w + s1.y * dd;

    for (int j = 0; j < m; j++) {
        int2 cv = g_cv[start + j];
        float v = __int_as_float(cv.y);
        uint2 hm = *((const uint2*)(g_hb + (size_t)cv.x * FEAT) + lane);
        float2 f0 = __bfloat1622float2(*(const __nv_bfloat162*)&hm.x);
        float2 f1 = __bfloat1622float2(*(const __nv_bfloat162*)&hm.y);
        acc.x = fmaf(f0.x, v, acc.x);
        acc.y = fmaf(f0.y, v, acc.y);
        acc.z = fmaf(f1.x, v, acc.z);
        acc.w = fmaf(f1.y, v, acc.w);
    }
    acc.x = fmaxf(acc.x, 0.f);
    acc.y = fmaxf(acc.y, 0.f);
    acc.z = fmaxf(acc.z, 0.f);
    acc.w = fmaxf(acc.w, 0.f);
    ((float4*)(g_a + (size_t)w * FEAT))[lane] = acc;
}

// ---------------- mean pool ----------------
__global__ void k_pool(const int* __restrict__ batch, int n) {
    int g = blockIdx.x;
    int f = threadIdx.x;
    int is64 = g_is64;
    int lo = 0, hi = n;
    while (lo < hi) { int mid = (lo + hi) >> 1; if (ld_idx(batch, mid, is64) < g) lo = mid + 1; else hi = mid; }
    int s = lo;
    hi = n;
    while (lo < hi) { int mid = (lo + hi) >> 1; if (ld_idx(batch, mid, is64) <= g) lo = mid + 1; else hi = mid; }
    int e = lo;
    float acc = 0.f;
    for (int i = s; i < e; i++) acc += g_a[(size_t)i * FEAT + f];
    int c = e - s;
    g_pool[g * FEAT + f] = acc / (float)(c > 0 ? c : 1);
}

// ---------------- MLP head ----------------
__global__ void k_mlp(const float* __restrict__ w1, const float* __restrict__ b1,
                      const float* __restrict__ w2, const float* __restrict__ b2,
                      float* __restrict__ out) {
    int g = blockIdx.x;
    int t = threadIdx.x;  // 128
    __shared__ float gs[128];
    __shared__ float ts[128];
    gs[t] = g_pool[g * FEAT + t];
    __syncthreads();
    float acc = b1[t];
#pragma unroll 8
    for (int k = 0; k < 128; k++) acc = fmaf(gs[k], w1[k * 128 + t], acc);
    ts[t] = fmaxf(acc, 0.f);
    __syncthreads();
    if (t < 10) {
        float o = b2[t];
#pragma unroll 8
        for (int j = 0; j < 128; j++) o = fmaf(ts[j], w2[j * 10 + t], o);
        out[g * 10 + t] = o;
    }
}

// ---------------- launcher ----------------
extern "C" void kernel_launch(void* const* d_in, const int* in_sizes, int n_in,
                              void* d_out, int out_size) {
    const float* x     = (const float*)d_in[0];
    const int*   ei    = (const int*)d_in[1];
    const int*   batch = (const int*)d_in[2];
    const float* W1 = (const float*)d_in[3];  const float* b1 = (const float*)d_in[4];
    const float* W2 = (const float*)d_in[5];  const float* b2 = (const float*)d_in[6];
    const float* W3 = (const float*)d_in[7];  const float* b3 = (const float*)d_in[8];
    const float* l1w = (const float*)d_in[9];  const float* l1b = (const float*)d_in[10];
    const float* l2w = (const float*)d_in[11]; const float* l2b = (const float*)d_in[12];
    float* out = (float*)d_out;

    int n = in_sizes[0] / FEAT;   // 100000
    int E = in_sizes[1] / 2;      // 3200000

    int nb = (n + 255) / 256;
    int eb = (E + 255) / 256;
    int gb = (n + 127) / 128;
    long long athreads = (long long)n * 32;
    int ab = (int)((athreads + 255) / 256);

    k_sniff  <<<1, 32>>>(ei);
    k_zero   <<<nb, 256>>>(n);
    k_count  <<<eb, 256>>>(ei, E, n);
    k_dis    <<<nb, 256>>>(n);
    k_scan1  <<<nb, 256>>>(n);
    k_scan2  <<<1, 512>>>(nb);
    k_scan3  <<<nb, 256>>>(n);
    k_fillcsr<<<eb, 256>>>(ei, E, n);

    k_gemmW<<<gb, 256>>>(x, W1, n);
    k_agg  <<<ab, 256>>>(b1, n);
    k_gemmW<<<gb, 256>>>(nullptr, W2, n);
    k_agg  <<<ab, 256>>>(b2, n);
    k_gemmW<<<gb, 256>>>(nullptr, W3, n);
    k_agg  <<<ab, 256>>>(b3, n);

    k_pool<<<N_GRAPHS, 128>>>(batch, n);
    k_mlp <<<N_GRAPHS, 128>>>(l1w, l1b, l2w, l2b, out);
}

// round 10
// speedup vs baseline: 1.2242x; 1.0562x over previous
#include <cuda_runtime.h>
#include <cuda_bf16.h>
#include <cstdint>

#define N_NODES   100000
#define N_EDGES   3200000
#define N_GRAPHS  256
#define FEAT      128

// ---------------- scratch ----------------
__device__ __align__(16) int   g_cnt[N_NODES];
__device__ __align__(16) int   g_fill[N_NODES];
__device__ __align__(16) int   g_rowstart[N_NODES];   // intra-block exclusive prefix
__device__ __align__(16) int   g_bsum[512];           // exclusive block sums
__device__ __align__(16) float g_dis[N_NODES];
__device__ __align__(16) int2  g_cv[N_EDGES];
__device__ __align__(16) __nv_bfloat16 g_hb[(size_t)N_NODES * FEAT];  // GEMM out (bf16, gathered)
__device__ __align__(16) float g_a[(size_t)N_NODES * FEAT];           // agg out (fp32, post-relu)
__device__ int g_is64;

__device__ __forceinline__ int ld_idx(const int* __restrict__ p, long long i, int is64) {
    if (is64) return (int)(((const long long*)p)[i]);
    return p[i];
}

// ---------------- dtype sniff ----------------
__global__ void k_sniff(const int* __restrict__ ei) {
    if (threadIdx.x == 0 && blockIdx.x == 0) {
        int odd = 0;
        for (int i = 1; i < 128; i += 2) odd |= ei[i];
        g_is64 = (odd == 0) ? 1 : 0;
    }
}

// ---------------- prep ----------------
__global__ void k_zero(int n) {
    int i = blockIdx.x * blockDim.x + threadIdx.x;
    if (i < n) { g_cnt[i] = 0; g_fill[i] = 0; }
}
__global__ void k_count(const int* __restrict__ ei, int E, int n) {
    int e = blockIdx.x * blockDim.x + threadIdx.x;
    if (e >= E) return;
    int d = ld_idx(ei, (long long)E + e, g_is64);
    if ((unsigned)d < (unsigned)n) atomicAdd(&g_cnt[d], 1);
}
// scan1 + dis fused
__global__ void k_scan1(int n) {
    __shared__ int s[256];
    int t = threadIdx.x;
    int i = blockIdx.x * 256 + t;
    int v = (i < n) ? g_cnt[i] : 0;
    if (i < n) g_dis[i] = rsqrtf((float)v + 1.0f);
    s[t] = v; __syncthreads();
    for (int off = 1; off < 256; off <<= 1) {
        int a = (t >= off) ? s[t - off] : 0;
        __syncthreads();
        s[t] += a;
        __syncthreads();
    }
    if (i < n) g_rowstart[i] = s[t] - v;
    if (t == 255) g_bsum[blockIdx.x] = s[255];
}
__global__ void k_scan2(int nb) {
    __shared__ int s[512];
    int t = threadIdx.x;
    int v = (t < nb) ? g_bsum[t] : 0;
    s[t] = v; __syncthreads();
    for (int off = 1; off < 512; off <<= 1) {
        int a = (t >= off) ? s[t - off] : 0;
        __syncthreads();
        s[t] += a;
        __syncthreads();
    }
    if (t < nb) g_bsum[t] = s[t] - v;
}
// fillcsr with inlined scan3 (rowstart[d] + bsum[d>>8])
__global__ void k_fillcsr(const int* __restrict__ ei, int E, int n) {
    int e = blockIdx.x * blockDim.x + threadIdx.x;
    if (e >= E) return;
    int is64 = g_is64;
    int s = ld_idx(ei, e, is64);
    int d = ld_idx(ei, (long long)E + e, is64);
    if ((unsigned)s >= (unsigned)n || (unsigned)d >= (unsigned)n) return;
    int pos = atomicAdd(&g_fill[d], 1);
    int base = g_rowstart[d] + g_bsum[d >> 8];
    float v = g_dis[s] * g_dis[d];
    g_cv[base + pos] = make_int2(s, __float_as_int(v));
}

// ---------------- GEMM: g_hb[n,128] = A[n,128] @ W[128,128] ----------------
// FFMA2 micro-kernel, 8 chunks of K=16, 2-stage smem double-buffer,
// register prefetch of next chunk issued before compute.
__global__ __launch_bounds__(256) void k_gemmW(const float* __restrict__ Ain,
                                               const float* __restrict__ W, int n) {
    __shared__ float As[2][16][129];
    __shared__ float Ws[2][16][128];
    const float* A = Ain ? Ain : g_a;
    int tid = threadIdx.x;
    int row0 = blockIdx.x << 7;
    int tx = tid & 15, ty = tid >> 4;
    int m0 = ty << 3, n0 = tx << 3;

    unsigned long long acc2[8][4];
#pragma unroll
    for (int i = 0; i < 8; i++)
#pragma unroll
        for (int j = 0; j < 4; j++) acc2[i][j] = 0ull;

    // per-chunk staging: A chunk = 128 rows x 16 k = 512 float4 (2/thread),
    //                    W chunk = 16 k x 128 n = 512 float4 (2/thread)
    int ia0 = tid * 2, ia1 = tid * 2 + 1;           // A float4 indices
    int ar0 = ia0 >> 2, ak0 = (ia0 & 3) << 2;       // row, k-offset
    int ar1 = ia1 >> 2, ak1 = (ia1 & 3) << 2;
    int wk0 = ia0 >> 5, wc0 = (ia0 & 31) << 2;      // k, col
    int wk1 = ia1 >> 5, wc1 = (ia1 & 31) << 2;

    float4 pa0, pa1, pw0, pw1;
    {
        // prefetch chunk 0
        pa0 = (row0 + ar0 < n) ? *(const float4*)(A + (size_t)(row0 + ar0) * FEAT + ak0)
                               : make_float4(0.f, 0.f, 0.f, 0.f);
        pa1 = (row0 + ar1 < n) ? *(const float4*)(A + (size_t)(row0 + ar1) * FEAT + ak1)
                               : make_float4(0.f, 0.f, 0.f, 0.f);
        pw0 = *(const float4*)(W + (size_t)wk0 * FEAT + wc0);
        pw1 = *(const float4*)(W + (size_t)wk1 * FEAT + wc1);
    }

#pragma unroll 1
    for (int c = 0; c < 8; c++) {
        int b = c & 1;
        // stage prefetched regs into smem (A transposed)
        As[b][ak0 + 0][ar0] = pa0.x;
        As[b][ak0 + 1][ar0] = pa0.y;
        As[b][ak0 + 2][ar0] = pa0.z;
        As[b][ak0 + 3][ar0] = pa0.w;
        As[b][ak1 + 0][ar1] = pa1.x;
        As[b][ak1 + 1][ar1] = pa1.y;
        As[b][ak1 + 2][ar1] = pa1.z;
        As[b][ak1 + 3][ar1] = pa1.w;
        *(float4*)(&Ws[b][wk0][wc0]) = pw0;
        *(float4*)(&Ws[b][wk1][wc1]) = pw1;
        __syncthreads();

        if (c < 7) {
            int k0 = (c + 1) << 4;
            pa0 = (row0 + ar0 < n) ? *(const float4*)(A + (size_t)(row0 + ar0) * FEAT + k0 + ak0)
                                   : make_float4(0.f, 0.f, 0.f, 0.f);
            pa1 = (row0 + ar1 < n) ? *(const float4*)(A + (size_t)(row0 + ar1) * FEAT + k0 + ak1)
                                   : make_float4(0.f, 0.f, 0.f, 0.f);
            pw0 = *(const float4*)(W + (size_t)(k0 + wk0) * FEAT + wc0);
            pw1 = *(const float4*)(W + (size_t)(k0 + wk1) * FEAT + wc1);
        }

#pragma unroll
        for (int k = 0; k < 16; k++) {
            ulonglong2 bq0 = *(ulonglong2*)(&Ws[b][k][n0]);
            ulonglong2 bq1 = *(ulonglong2*)(&Ws[b][k][n0 + 4]);
            unsigned long long bp0 = bq0.x, bp1 = bq0.y, bp2 = bq1.x, bp3 = bq1.y;
#pragma unroll
            for (int i = 0; i < 8; i++) {
                float a = As[b][k][m0 + i];
                unsigned long long ap;
                asm("mov.b64 %0, {%1, %1};" : "=l"(ap) : "f"(a));
                asm("fma.rn.f32x2 %0, %1, %2, %0;" : "+l"(acc2[i][0]) : "l"(ap), "l"(bp0));
                asm("fma.rn.f32x2 %0, %1, %2, %0;" : "+l"(acc2[i][1]) : "l"(ap), "l"(bp1));
                asm("fma.rn.f32x2 %0, %1, %2, %0;" : "+l"(acc2[i][2]) : "l"(ap), "l"(bp2));
                asm("fma.rn.f32x2 %0, %1, %2, %0;" : "+l"(acc2[i][3]) : "l"(ap), "l"(bp3));
            }
        }
        __syncthreads();
    }

#pragma unroll
    for (int i = 0; i < 8; i++) {
        int r = row0 + m0 + i;
        if (r < n) {
            uint32_t o[4];
#pragma unroll
            for (int j = 0; j < 4; j++) {
                uint32_t lo, hi;
                asm("mov.b64 {%0, %1}, %2;" : "=r"(lo), "=r"(hi) : "l"(acc2[i][j]));
                __nv_bfloat162 p = __floats2bfloat162_rn(__uint_as_float(lo), __uint_as_float(hi));
                o[j] = *(uint32_t*)&p;
            }
            *(uint4*)(g_hb + (size_t)r * FEAT + n0) = make_uint4(o[0], o[1], o[2], o[3]);
        }
    }
}

// ---------------- aggregation: g_a[i] = relu(b + dis^2*hb[i] + sum val*hb[col]) ----------------
__global__ void k_agg(const float* __restrict__ bias, int n) {
    int w = (blockIdx.x * blockDim.x + threadIdx.x) >> 5;
    int lane = threadIdx.x & 31;
    if (w >= n) return;
    int start = g_rowstart[w] + g_bsum[w >> 8];
    int m = g_cnt[w];
    float d = g_dis[w];
    float dd = d * d;

    uint2 sv = *((const uint2*)(g_hb + (size_t)w * FEAT) + lane);
    float2 s0 = __bfloat1622float2(*(const __nv_bfloat162*)&sv.x);
    float2 s1 = __bfloat1622float2(*(const __nv_bfloat162*)&sv.y);
    float4 bv = __ldg((const float4*)bias + lane);
    float4 acc;
    acc.x = bv.x + s0.x * dd;
    acc.y = bv.y + s0.y * dd;
    acc.z = bv.z + s1.x * dd;
    acc.w = bv.w + s1.y * dd;

    for (int j = 0; j < m; j++) {
        int2 cv = g_cv[start + j];
        float v = __int_as_float(cv.y);
        uint2 hm = *((const uint2*)(g_hb + (size_t)cv.x * FEAT) + lane);
        float2 f0 = __bfloat1622float2(*(const __nv_bfloat162*)&hm.x);
        float2 f1 = __bfloat1622float2(*(const __nv_bfloat162*)&hm.y);
        acc.x = fmaf(f0.x, v, acc.x);
        acc.y = fmaf(f0.y, v, acc.y);
        acc.z = fmaf(f1.x, v, acc.z);
        acc.w = fmaf(f1.y, v, acc.w);
    }
    acc.x = fmaxf(acc.x, 0.f);
    acc.y = fmaxf(acc.y, 0.f);
    acc.z = fmaxf(acc.z, 0.f);
    acc.w = fmaxf(acc.w, 0.f);
    ((float4*)(g_a + (size_t)w * FEAT))[lane] = acc;
}

// ---------------- fused mean-pool + MLP head ----------------
__global__ void k_poolmlp(const int* __restrict__ batch, int n,
                          const float* __restrict__ w1, const float* __restrict__ b1,
                          const float* __restrict__ w2, const float* __restrict__ b2,
                          float* __restrict__ out) {
    int g = blockIdx.x;
    int t = threadIdx.x;  // 128
    int is64 = g_is64;
    __shared__ float gs[128];
    __shared__ float ts[128];

    int lo = 0, hi = n;
    while (lo < hi) { int mid = (lo + hi) >> 1; if (ld_idx(batch, mid, is64) < g) lo = mid + 1; else hi = mid; }
    int s = lo;
    hi = n;
    while (lo < hi) { int mid = (lo + hi) >> 1; if (ld_idx(batch, mid, is64) <= g) lo = mid + 1; else hi = mid; }
    int e = lo;
    float acc = 0.f;
    for (int i = s; i < e; i++) acc += g_a[(size_t)i * FEAT + t];
    int c = e - s;
    gs[t] = acc / (float)(c > 0 ? c : 1);
    __syncthreads();

    float h = b1[t];
#pragma unroll 8
    for (int k = 0; k < 128; k++) h = fmaf(gs[k], w1[k * 128 + t], h);
    ts[t] = fmaxf(h, 0.f);
    __syncthreads();
    if (t < 10) {
        float o = b2[t];
#pragma unroll 8
        for (int j = 0; j < 128; j++) o = fmaf(ts[j], w2[j * 10 + t], o);
        out[g * 10 + t] = o;
    }
}

// ---------------- launcher ----------------
extern "C" void kernel_launch(void* const* d_in, const int* in_sizes, int n_in,
                              void* d_out, int out_size) {
    const float* x     = (const float*)d_in[0];
    const int*   ei    = (const int*)d_in[1];
    const int*   batch = (const int*)d_in[2];
    const float* W1 = (const float*)d_in[3];  const float* b1 = (const float*)d_in[4];
    const float* W2 = (const float*)d_in[5];  const float* b2 = (const float*)d_in[6];
    const float* W3 = (const float*)d_in[7];  const float* b3 = (const float*)d_in[8];
    const float* l1w = (const float*)d_in[9];  const float* l1b = (const float*)d_in[10];
    const float* l2w = (const float*)d_in[11]; const float* l2b = (const float*)d_in[12];
    float* out = (float*)d_out;

    int n = in_sizes[0] / FEAT;   // 100000
    int E = in_sizes[1] / 2;      // 3200000

    int nb = (n + 255) / 256;
    int eb = (E + 255) / 256;
    int gb = (n + 127) / 128;
    long long athreads = (long long)n * 32;
    int ab = (int)((athreads + 255) / 256);

    // order chosen so gemm1 is my 4th launch (ncu -s 5 profiles it)
    k_sniff  <<<1, 32>>>(ei);
    k_zero   <<<nb, 256>>>(n);
    k_count  <<<eb, 256>>>(ei, E, n);
    k_gemmW  <<<gb, 256>>>(x, W1, n);       // layer-1 GEMM (independent of CSR prep)
    k_scan1  <<<nb, 256>>>(n);
    k_scan2  <<<1, 512>>>(nb);
    k_fillcsr<<<eb, 256>>>(ei, E, n);

    k_agg  <<<ab, 256>>>(b1, n);
    k_gemmW<<<gb, 256>>>(nullptr, W2, n);
    k_agg  <<<ab, 256>>>(b2, n);
    k_gemmW<<<gb, 256>>>(nullptr, W3, n);
    k_agg  <<<ab, 256>>>(b3, n);

    k_poolmlp<<<N_GRAPHS, 128>>>(batch, n, l1w, l1b, l2w, l2b, out);
}

// round 11
// speedup vs baseline: 1.2400x; 1.0129x over previous
#include <cuda_runtime.h>
#include <cuda_bf16.h>
#include <cstdint>

#define N_NODES   100000
#define N_EDGES   3200000
#define N_GRAPHS  256
#define FEAT      128
#define APITCH    132   // fp32 smem pitch: multiple of 4 -> 16B-aligned float4 rows

// ---------------- scratch ----------------
__device__ __align__(16) int   g_cnt[N_NODES];
__device__ __align__(16) int   g_fill[N_NODES];
__device__ __align__(16) int   g_rowstart[N_NODES];   // intra-block exclusive prefix
__device__ __align__(16) int   g_bsum[512];           // exclusive block sums
__device__ __align__(16) float g_dis[N_NODES];
__device__ __align__(16) int2  g_cv[N_EDGES];
__device__ __align__(16) __nv_bfloat16 g_hb[(size_t)N_NODES * FEAT];  // GEMM out (bf16, gathered)
__device__ __align__(16) float g_a[(size_t)N_NODES * FEAT];           // agg out (fp32, post-relu)
__device__ int g_is64;

__device__ __forceinline__ int ld_idx(const int* __restrict__ p, long long i, int is64) {
    if (is64) return (int)(((const long long*)p)[i]);
    return p[i];
}

// ---------------- dtype sniff ----------------
__global__ void k_sniff(const int* __restrict__ ei) {
    if (threadIdx.x == 0 && blockIdx.x == 0) {
        int odd = 0;
        for (int i = 1; i < 128; i += 2) odd |= ei[i];
        g_is64 = (odd == 0) ? 1 : 0;
    }
}

// ---------------- prep ----------------
__global__ void k_zero(int n) {
    int i = blockIdx.x * blockDim.x + threadIdx.x;
    if (i < n) { g_cnt[i] = 0; g_fill[i] = 0; }
}
__global__ void k_count(const int* __restrict__ ei, int E, int n) {
    int e = blockIdx.x * blockDim.x + threadIdx.x;
    if (e >= E) return;
    int d = ld_idx(ei, (long long)E + e, g_is64);
    if ((unsigned)d < (unsigned)n) atomicAdd(&g_cnt[d], 1);
}
// scan1 + dis fused
__global__ void k_scan1(int n) {
    __shared__ int s[256];
    int t = threadIdx.x;
    int i = blockIdx.x * 256 + t;
    int v = (i < n) ? g_cnt[i] : 0;
    if (i < n) g_dis[i] = rsqrtf((float)v + 1.0f);
    s[t] = v; __syncthreads();
    for (int off = 1; off < 256; off <<= 1) {
        int a = (t >= off) ? s[t - off] : 0;
        __syncthreads();
        s[t] += a;
        __syncthreads();
    }
    if (i < n) g_rowstart[i] = s[t] - v;
    if (t == 255) g_bsum[blockIdx.x] = s[255];
}
__global__ void k_scan2(int nb) {
    __shared__ int s[512];
    int t = threadIdx.x;
    int v = (t < nb) ? g_bsum[t] : 0;
    s[t] = v; __syncthreads();
    for (int off = 1; off < 512; off <<= 1) {
        int a = (t >= off) ? s[t - off] : 0;
        __syncthreads();
        s[t] += a;
        __syncthreads();
    }
    if (t < nb) g_bsum[t] = s[t] - v;
}
// fillcsr with inlined scan3 (rowstart[d] + bsum[d>>8])
__global__ void k_fillcsr(const int* __restrict__ ei, int E, int n) {
    int e = blockIdx.x * blockDim.x + threadIdx.x;
    if (e >= E) return;
    int is64 = g_is64;
    int s = ld_idx(ei, e, is64);
    int d = ld_idx(ei, (long long)E + e, is64);
    if ((unsigned)s >= (unsigned)n || (unsigned)d >= (unsigned)n) return;
    int pos = atomicAdd(&g_fill[d], 1);
    int base = g_rowstart[d] + g_bsum[d >> 8];
    float v = g_dis[s] * g_dis[d];
    g_cv[base + pos] = make_int2(s, __float_as_int(v));
}

// ---------------- GEMM: g_hb[n,128] = A[n,128] @ W[128,128] ----------------
// FFMA2 micro-kernel; A read from smem via 2x LDS.128 (broadcast, 1 wavefront);
// 8 chunks of K=16, 2-stage smem double-buffer with register prefetch.
__global__ __launch_bounds__(256) void k_gemmW(const float* __restrict__ Ain,
                                               const float* __restrict__ W, int n) {
    __shared__ float As[2][16][APITCH];
    __shared__ float Ws[2][16][128];
    const float* A = Ain ? Ain : g_a;
    int tid = threadIdx.x;
    int row0 = blockIdx.x << 7;
    int tx = tid & 15, ty = tid >> 4;
    int m0 = ty << 3, n0 = tx << 3;

    unsigned long long acc2[8][4];
#pragma unroll
    for (int i = 0; i < 8; i++)
#pragma unroll
        for (int j = 0; j < 4; j++) acc2[i][j] = 0ull;

    // staging indices: A chunk = 128 rows x 16 k = 512 float4 (2/thread),
    //                  W chunk = 16 k x 128 n = 512 float4 (2/thread)
    int ia0 = tid * 2, ia1 = tid * 2 + 1;
    int ar0 = ia0 >> 2, ak0 = (ia0 & 3) << 2;
    int ar1 = ia1 >> 2, ak1 = (ia1 & 3) << 2;
    int wk0 = ia0 >> 5, wc0 = (ia0 & 31) << 2;
    int wk1 = ia1 >> 5, wc1 = (ia1 & 31) << 2;

    float4 pa0, pa1, pw0, pw1;
    pa0 = (row0 + ar0 < n) ? *(const float4*)(A + (size_t)(row0 + ar0) * FEAT + ak0)
                           : make_float4(0.f, 0.f, 0.f, 0.f);
    pa1 = (row0 + ar1 < n) ? *(const float4*)(A + (size_t)(row0 + ar1) * FEAT + ak1)
                           : make_float4(0.f, 0.f, 0.f, 0.f);
    pw0 = *(const float4*)(W + (size_t)wk0 * FEAT + wc0);
    pw1 = *(const float4*)(W + (size_t)wk1 * FEAT + wc1);

#pragma unroll 1
    for (int c = 0; c < 8; c++) {
        int b = c & 1;
        As[b][ak0 + 0][ar0] = pa0.x;
        As[b][ak0 + 1][ar0] = pa0.y;
        As[b][ak0 + 2][ar0] = pa0.z;
        As[b][ak0 + 3][ar0] = pa0.w;
        As[b][ak1 + 0][ar1] = pa1.x;
        As[b][ak1 + 1][ar1] = pa1.y;
        As[b][ak1 + 2][ar1] = pa1.z;
        As[b][ak1 + 3][ar1] = pa1.w;
        *(float4*)(&Ws[b][wk0][wc0]) = pw0;
        *(float4*)(&Ws[b][wk1][wc1]) = pw1;
        __syncthreads();

        if (c < 7) {
            int k0 = (c + 1) << 4;
            pa0 = (row0 + ar0 < n) ? *(const float4*)(A + (size_t)(row0 + ar0) * FEAT + k0 + ak0)
                                   : make_float4(0.f, 0.f, 0.f, 0.f);
            pa1 = (row0 + ar1 < n) ? *(const float4*)(A + (size_t)(row0 + ar1) * FEAT + k0 + ak1)
                                   : make_float4(0.f, 0.f, 0.f, 0.f);
            pw0 = *(const float4*)(W + (size_t)(k0 + wk0) * FEAT + wc0);
            pw1 = *(const float4*)(W + (size_t)(k0 + wk1) * FEAT + wc1);
        }

#pragma unroll
        for (int k = 0; k < 16; k++) {
            // A: 2x LDS.128 broadcast (2 distinct 16B addrs per warp -> 1 wavefront)
            float4 a0 = *(float4*)(&As[b][k][m0]);
            float4 a1 = *(float4*)(&As[b][k][m0 + 4]);
            float av[8] = {a0.x, a0.y, a0.z, a0.w, a1.x, a1.y, a1.z, a1.w};
            // W: 2x LDS.128
            ulonglong2 bq0 = *(ulonglong2*)(&Ws[b][k][n0]);
            ulonglong2 bq1 = *(ulonglong2*)(&Ws[b][k][n0 + 4]);
            unsigned long long bp0 = bq0.x, bp1 = bq0.y, bp2 = bq1.x, bp3 = bq1.y;
#pragma unroll
            for (int i = 0; i < 8; i++) {
                unsigned long long ap;
                asm("mov.b64 %0, {%1, %1};" : "=l"(ap) : "f"(av[i]));
                asm("fma.rn.f32x2 %0, %1, %2, %0;" : "+l"(acc2[i][0]) : "l"(ap), "l"(bp0));
                asm("fma.rn.f32x2 %0, %1, %2, %0;" : "+l"(acc2[i][1]) : "l"(ap), "l"(bp1));
                asm("fma.rn.f32x2 %0, %1, %2, %0;" : "+l"(acc2[i][2]) : "l"(ap), "l"(bp2));
                asm("fma.rn.f32x2 %0, %1, %2, %0;" : "+l"(acc2[i][3]) : "l"(ap), "l"(bp3));
            }
        }
        __syncthreads();
    }

#pragma unroll
    for (int i = 0; i < 8; i++) {
        int r = row0 + m0 + i;
        if (r < n) {
            uint32_t o[4];
#pragma unroll
            for (int j = 0; j < 4; j++) {
                uint32_t lo, hi;
                asm("mov.b64 {%0, %1}, %2;" : "=r"(lo), "=r"(hi) : "l"(acc2[i][j]));
                __nv_bfloat162 p = __floats2bfloat162_rn(__uint_as_float(lo), __uint_as_float(hi));
                o[j] = *(uint32_t*)&p;
            }
            *(uint4*)(g_hb + (size_t)r * FEAT + n0) = make_uint4(o[0], o[1], o[2], o[3]);
        }
    }
}

// ---------------- aggregation: g_a[i] = relu(b + dis^2*hb[i] + sum val*hb[col]) ----------------
__global__ void k_agg(const float* __restrict__ bias, int n) {
    int w = (blockIdx.x * blockDim.x + threadIdx.x) >> 5;
    int lane = threadIdx.x & 31;
    if (w >= n) return;
    int start = g_rowstart[w] + g_bsum[w >> 8];
    int m = g_cnt[w];
    float d = g_dis[w];
    float dd = d * d;

    uint2 sv = *((const uint2*)(g_hb + (size_t)w * FEAT) + lane);
    float2 s0 = __bfloat1622float2(*(const __nv_bfloat162*)&sv.x);
    float2 s1 = __bfloat1622float2(*(const __nv_bfloat162*)&sv.y);
    float4 bv = __ldg((const float4*)bias + lane);
    float4 acc;
    acc.x = bv.x + s0.x * dd;
    acc.y = bv.y + s0.y * dd;
    acc.z = bv.z + s1.x * dd;
    acc.w = bv.w + s1.y * dd;

    for (int j = 0; j < m; j++) {
        int2 cv = g_cv[start + j];
        float v = __int_as_float(cv.y);
        uint2 hm = *((const uint2*)(g_hb + (size_t)cv.x * FEAT) + lane);
        float2 f0 = __bfloat1622float2(*(const __nv_bfloat162*)&hm.x);
        float2 f1 = __bfloat1622float2(*(const __nv_bfloat162*)&hm.y);
        acc.x = fmaf(f0.x, v, acc.x);
        acc.y = fmaf(f0.y, v, acc.y);
        acc.z = fmaf(f1.x, v, acc.z);
        acc.w = fmaf(f1.y, v, acc.w);
    }
    acc.x = fmaxf(acc.x, 0.f);
    acc.y = fmaxf(acc.y, 0.f);
    acc.z = fmaxf(acc.z, 0.f);
    acc.w = fmaxf(acc.w, 0.f);
    ((float4*)(g_a + (size_t)w * FEAT))[lane] = acc;
}

// ---------------- fused mean-pool + MLP head ----------------
__global__ void k_poolmlp(const int* __restrict__ batch, int n,
                          const float* __restrict__ w1, const float* __restrict__ b1,
                          const float* __restrict__ w2, const float* __restrict__ b2,
                          float* __restrict__ out) {
    int g = blockIdx.x;
    int t = threadIdx.x;  // 128
    int is64 = g_is64;
    __shared__ float gs[128];
    __shared__ float ts[128];

    int lo = 0, hi = n;
    while (lo < hi) { int mid = (lo + hi) >> 1; if (ld_idx(batch, mid, is64) < g) lo = mid + 1; else hi = mid; }
    int s = lo;
    hi = n;
    while (lo < hi) { int mid = (lo + hi) >> 1; if (ld_idx(batch, mid, is64) <= g) lo = mid + 1; else hi = mid; }
    int e = lo;
    float acc = 0.f;
    for (int i = s; i < e; i++) acc += g_a[(size_t)i * FEAT + t];
    int c = e - s;
    gs[t] = acc / (float)(c > 0 ? c : 1);
    __syncthreads();

    float h = b1[t];
#pragma unroll 8
    for (int k = 0; k < 128; k++) h = fmaf(gs[k], w1[k * 128 + t], h);
    ts[t] = fmaxf(h, 0.f);
    __syncthreads();
    if (t < 10) {
        float o = b2[t];
#pragma unroll 8
        for (int j = 0; j < 128; j++) o = fmaf(ts[j], w2[j * 10 + t], o);
        out[g * 10 + t] = o;
    }
}

// ---------------- launcher ----------------
extern "C" void kernel_launch(void* const* d_in, const int* in_sizes, int n_in,
                              void* d_out, int out_size) {
    const float* x     = (const float*)d_in[0];
    const int*   ei    = (const int*)d_in[1];
    const int*   batch = (const int*)d_in[2];
    const float* W1 = (const float*)d_in[3];  const float* b1 = (const float*)d_in[4];
    const float* W2 = (const float*)d_in[5];  const float* b2 = (const float*)d_in[6];
    const float* W3 = (const float*)d_in[7];  const float* b3 = (const float*)d_in[8];
    const float* l1w = (const float*)d_in[9];  const float* l1b = (const float*)d_in[10];
    const float* l2w = (const float*)d_in[11]; const float* l2b = (const float*)d_in[12];
    float* out = (float*)d_out;

    int n = in_sizes[0] / FEAT;   // 100000
    int E = in_sizes[1] / 2;      // 3200000

    int nb = (n + 255) / 256;
    int eb = (E + 255) / 256;
    int gb = (n + 127) / 128;
    long long athreads = (long long)n * 32;
    int ab = (int)((athreads + 255) / 256);

    // order keeps gemm1 as my 4th launch (ncu -s 5 profiles it)
    k_sniff  <<<1, 32>>>(ei);
    k_zero   <<<nb, 256>>>(n);
    k_count  <<<eb, 256>>>(ei, E, n);
    k_gemmW  <<<gb, 256>>>(x, W1, n);       // layer-1 GEMM (independent of CSR prep)
    k_scan1  <<<nb, 256>>>(n);
    k_scan2  <<<1, 512>>>(nb);
    k_fillcsr<<<eb, 256>>>(ei, E, n);

    k_agg  <<<ab, 256>>>(b1, n);
    k_gemmW<<<gb, 256>>>(nullptr, W2, n);
    k_agg  <<<ab, 256>>>(b2, n);
    k_gemmW<<<gb, 256>>>(nullptr, W3, n);
    k_agg  <<<ab, 256>>>(b3, n);

    k_poolmlp<<<N_GRAPHS, 128>>>(batch, n, l1w, l1b, l2w, l2b, out);
}